// round 3
// baseline (speedup 1.0000x reference)
#include <cuda_runtime.h>
#include <cuda_fp16.h>

#define NR 16384
#define DIM 64
// exp(sim/T) = exp2(sim * 1/(T*ln2)) = exp2(sim * 2.885390...), T=0.5
// scale each normalized vector by sqrt(2.885390...) so the dot IS the exp2 arg.
#define SQRT_SCALE 1.6986436029926783f
#define E2C 7.389056098930650f   // exp(1/T) = e^2, exact diagonal term

__device__ __half2 g_Y[NR * (DIM / 2)];   // normalized+scaled rows, f16
__device__ float   g_RS[NR];              // row sums of exp2(arg)
__device__ float   g_part[NR / 256];      // per-block ratio partial sums

// ---------------------------------------------------------------------------
// Kernel 1: per-row L2 normalize + scale, write f16. One warp per row.
// ---------------------------------------------------------------------------
__global__ void k_normalize(const float* __restrict__ x) {
    int w    = (blockIdx.x * blockDim.x + threadIdx.x) >> 5;   // row
    int lane = threadIdx.x & 31;
    float2 v = ((const float2*)x)[w * 32 + lane];
    float ss = v.x * v.x + v.y * v.y;
#pragma unroll
    for (int o = 16; o > 0; o >>= 1) ss += __shfl_xor_sync(0xffffffffu, ss, o);
    float s = SQRT_SCALE * rsqrtf(fmaxf(ss, 1e-16f));
    g_Y[w * 32 + lane] = __floats2half2_rn(v.x * s, v.y * s);
}

// ---------------------------------------------------------------------------
// Kernel 2: fused  G = Y Y^T  ->  exp2  ->  row sums.
// Grid: 128 CTAs, each owns 128 rows. Loop over 128 j-chunks of 128 columns.
// 8 warps = 2 row-groups (64 rows) x 4 column-groups.
// Smem tiles padded to stride 72 halves (144B = 36 banks) -> conflict-free
// b32 fragment loads. A tile buffer is reused as the second B buffer
// (A fragments live in registers after the prologue).
// ---------------------------------------------------------------------------
__device__ __forceinline__ void cp16(void* dst, const void* src) {
    unsigned d = (unsigned)__cvta_generic_to_shared(dst);
    asm volatile("cp.async.ca.shared.global [%0], [%1], 16;\n" ::"r"(d), "l"(src));
}

__device__ __forceinline__ void prefetch_tile(__half* buf, int rowbase, int tid) {
    const float4* src = (const float4*)g_Y;   // 8 halves per float4, 8 per row
#pragma unroll
    for (int it = 0; it < 4; it++) {
        int u   = tid + it * 256;             // 0..1023
        int row = u >> 3;
        int kc  = u & 7;
        cp16(buf + row * 72 + kc * 8, src + (rowbase + row) * 8 + kc);
    }
}

__global__ void __launch_bounds__(256, 1) k_main() {
    __shared__ __align__(16) __half smB[128 * 72];
    __shared__ __align__(16) __half smA[128 * 72];
    __shared__ float partials[128][4];

    int tid  = threadIdx.x;
    int warp = tid >> 5, lane = tid & 31;
    int r = warp >> 2, c = warp & 3;          // row-group / column-group
    int rbase = r * 64;
    int lr  = lane >> 2;                      // 0..7
    int lk2 = (lane & 3) * 2;                 // 0,2,4,6

    // Prologue: async-load A tile (this CTA's rows) and j-chunk 0.
    prefetch_tile(smA, blockIdx.x * 128, tid);
    asm volatile("cp.async.commit_group;\n");
    prefetch_tile(smB, 0, tid);
    asm volatile("cp.async.commit_group;\n");
    asm volatile("cp.async.wait_group 1;\n");   // A tile ready
    __syncthreads();

    // A fragments: m16n8k16 layout. a0:(row,k) a1:(row+8,k) a2:(row,k+8) a3:(row+8,k+8)
    unsigned a[4][4][4];
#pragma unroll
    for (int mf = 0; mf < 4; mf++) {
#pragma unroll
        for (int kf = 0; kf < 4; kf++) {
            const __half* p = smA + (rbase + mf * 16 + lr) * 72 + kf * 16 + lk2;
            a[mf][kf][0] = *(const unsigned*)(p);
            a[mf][kf][1] = *(const unsigned*)(p + 8 * 72);
            a[mf][kf][2] = *(const unsigned*)(p + 8);
            a[mf][kf][3] = *(const unsigned*)(p + 8 * 72 + 8);
        }
    }
    __syncthreads();   // everyone done reading smA before it becomes B-buffer 1

    unsigned racc0[4] = {0, 0, 0, 0};   // f16x2 row accumulators (row lr)
    unsigned racc1[4] = {0, 0, 0, 0};   // (row lr+8)
    float facc[8] = {0.f, 0.f, 0.f, 0.f, 0.f, 0.f, 0.f, 0.f};

    for (int t = 0; t < 128; t++) {
        if (t + 1 < 128) {
            __half* nb = (t & 1) ? smB : smA;   // buffer for chunk t+1
            prefetch_tile(nb, (t + 1) * 128, tid);
            asm volatile("cp.async.commit_group;\n");
            asm volatile("cp.async.wait_group 1;\n");   // chunk t complete
        } else {
            asm volatile("cp.async.wait_group 0;\n");
        }
        __syncthreads();

        const __half* B = (t & 1) ? smA : smB;
#pragma unroll
        for (int s = 0; s < 4; s++) {
            int n0 = (c + s * 4) * 8;
            // B fragments: b0:{B[k][n],B[k+1][n]} = consecutive k for n=lane/4
            unsigned b[4][2];
            const __half* bp = B + (n0 + lr) * 72 + lk2;
#pragma unroll
            for (int kf = 0; kf < 4; kf++) {
                b[kf][0] = *(const unsigned*)(bp + kf * 16);
                b[kf][1] = *(const unsigned*)(bp + kf * 16 + 8);
            }
#pragma unroll
            for (int mf = 0; mf < 4; mf++) {
                unsigned d0 = 0, d1 = 0;
#pragma unroll
                for (int kf = 0; kf < 4; kf++) {
                    asm("mma.sync.aligned.m16n8k16.row.col.f16.f16.f16.f16 "
                        "{%0,%1},{%2,%3,%4,%5},{%6,%7},{%0,%1};\n"
                        : "+r"(d0), "+r"(d1)
                        : "r"(a[mf][kf][0]), "r"(a[mf][kf][1]),
                          "r"(a[mf][kf][2]), "r"(a[mf][kf][3]),
                          "r"(b[kf][0]), "r"(b[kf][1]));
                }
                // d0 = (row, 2 cols), d1 = (row+8, 2 cols): exp2 then row-add
                unsigned e0, e1;
                asm("ex2.approx.f16x2 %0, %1;" : "=r"(e0) : "r"(d0));
                asm("ex2.approx.f16x2 %0, %1;" : "=r"(e1) : "r"(d1));
                asm("add.f16x2 %0, %0, %1;" : "+r"(racc0[mf]) : "r"(e0));
                asm("add.f16x2 %0, %0, %1;" : "+r"(racc1[mf]) : "r"(e1));
            }
        }
        // Flush f16x2 partials (max 8 terms, <=145 in magnitude) to fp32.
#pragma unroll
        for (int mf = 0; mf < 4; mf++) {
            __half2 h0 = *reinterpret_cast<__half2*>(&racc0[mf]);
            __half2 h1 = *reinterpret_cast<__half2*>(&racc1[mf]);
            float2 f0 = __half22float2(h0);
            float2 f1 = __half22float2(h1);
            facc[mf * 2 + 0] += f0.x + f0.y;
            facc[mf * 2 + 1] += f1.x + f1.y;
            racc0[mf] = 0;
            racc1[mf] = 0;
        }
        __syncthreads();   // compute done before next prefetch overwrites buffer
    }

    // Reduce across the 4 lanes sharing each row, stash per column-group.
#pragma unroll
    for (int mf = 0; mf < 4; mf++) {
#pragma unroll
        for (int h = 0; h < 2; h++) {
            float v = facc[mf * 2 + h];
            v += __shfl_xor_sync(0xffffffffu, v, 1);
            v += __shfl_xor_sync(0xffffffffu, v, 2);
            if ((lane & 3) == 0)
                partials[rbase + mf * 16 + h * 8 + lr][c] = v;
        }
    }
    __syncthreads();
    if (tid < 128) {
        float* p = partials[tid];
        g_RS[blockIdx.x * 128 + tid] = p[0] + p[1] + p[2] + p[3];
    }
}

// ---------------------------------------------------------------------------
// Kernel 3: numerator (positive pair), ratio, deterministic block partials.
// ---------------------------------------------------------------------------
__global__ void k_final() {
    __shared__ float red[8];
    int i = blockIdx.x * 256 + threadIdx.x;
    int j = i ^ 1;
    const __half2* yi = g_Y + i * 32;
    const __half2* yj = g_Y + j * 32;
    float dot = 0.f;
#pragma unroll
    for (int k = 0; k < 32; k++) {
        float2 av = __half22float2(yi[k]);
        float2 bv = __half22float2(yj[k]);
        dot += av.x * bv.x + av.y * bv.y;
    }
    float num   = exp2f(dot);                 // dot already carries 1/(T ln2)
    float ratio = num / (g_RS[i] - E2C);

    int lane = threadIdx.x & 31, w = threadIdx.x >> 5;
#pragma unroll
    for (int o = 16; o > 0; o >>= 1) ratio += __shfl_xor_sync(0xffffffffu, ratio, o);
    if (lane == 0) red[w] = ratio;
    __syncthreads();
    if (threadIdx.x < 8) {
        float v = red[threadIdx.x];
#pragma unroll
        for (int o = 4; o > 0; o >>= 1) v += __shfl_xor_sync(0x000000ffu, v, o);
        if (threadIdx.x == 0) g_part[blockIdx.x] = v;
    }
}

// ---------------------------------------------------------------------------
// Kernel 4: final deterministic reduce of 64 partials -> loss.
// ---------------------------------------------------------------------------
__global__ void k_loss(float* __restrict__ out) {
    __shared__ float w2[2];
    int t = threadIdx.x;            // 64 threads
    float v = g_part[t];
#pragma unroll
    for (int o = 16; o > 0; o >>= 1) v += __shfl_xor_sync(0xffffffffu, v, o);
    if ((t & 31) == 0) w2[t >> 5] = v;
    __syncthreads();
    if (t == 0) out[0] = -logf((w2[0] + w2[1]) * (1.0f / (float)NR));
}

// ---------------------------------------------------------------------------
extern "C" void kernel_launch(void* const* d_in, const int* in_sizes, int n_in,
                              void* d_out, int out_size) {
    const float* x = (const float*)d_in[0];
    k_normalize<<<NR / 8, 256>>>(x);     // 8 rows (warps) per block
    k_main<<<NR / 128, 256>>>();
    k_final<<<NR / 256, 256>>>();
    k_loss<<<1, 64>>>((float*)d_out);
}

// round 4
// speedup vs baseline: 1.2041x; 1.2041x over previous
#include <cuda_runtime.h>
#include <cuda_fp16.h>

#define NR 16384
#define DIM 64
#define NT 128                    // 128-row strips
#define TOT (NT * (NT + 1) / 2)   // 8256 triangle tiles
// exp(sim/T) = exp2(sim * 1/(T*ln2)), T=0.5 -> scale rows by sqrt(2.885390...)
#define SQRT_SCALE 1.6986436029926783f
#define E2C 7.389056098930650f    // exp(1/T) = e^2, exact diagonal term

#define SM_A_OFF 0                // halves
#define SM_TILE 9216              // 128*72 halves per buffer
#define SM_B_BYTE 36864
#define SM_RED_BYTE 73728
#define SM_CRED_BYTE 75776
#define SM_TOTAL_BYTE 76800

__device__ __half2 g_Y[NR * (DIM / 2)];   // normalized+scaled rows, f16
__device__ float   g_RS[NR];              // row sums of exp2(arg)
__device__ float   g_part[NR / 256];      // per-block ratio partial sums

// ---------------------------------------------------------------------------
// Kernel 1: per-row L2 normalize + scale, write f16; also zero g_RS.
// ---------------------------------------------------------------------------
__global__ void k_normalize(const float* __restrict__ x) {
    int w    = (blockIdx.x * blockDim.x + threadIdx.x) >> 5;   // row
    int lane = threadIdx.x & 31;
    float2 v = ((const float2*)x)[w * 32 + lane];
    float ss = v.x * v.x + v.y * v.y;
#pragma unroll
    for (int o = 16; o > 0; o >>= 1) ss += __shfl_xor_sync(0xffffffffu, ss, o);
    float s = SQRT_SCALE * rsqrtf(fmaxf(ss, 1e-16f));
    g_Y[w * 32 + lane] = __floats2half2_rn(v.x * s, v.y * s);
    if (lane == 0) g_RS[w] = 0.f;            // fresh accumulators each launch
}

// ---------------------------------------------------------------------------
// Kernel 2: triangular fused  exp2(Y Y^T)  ->  row sums (via row+col sums).
// 148 persistent CTAs, contiguous ranges of the 8256 (I<=J) 128x128 tiles.
// Per tile: 8 warps = 2 row-groups x 4 col-groups; f16-accum mma.16816,
// ex2.approx.f16x2 on accum frags, f16x2 row+col partials flushed to fp32,
// shfl+smem reduced, atomicAdd into g_RS (rows->strip I, cols->strip J).
// ---------------------------------------------------------------------------
__device__ __forceinline__ void cp16(void* dst, const void* src) {
    unsigned d = (unsigned)__cvta_generic_to_shared(dst);
    asm volatile("cp.async.ca.shared.global [%0], [%1], 16;\n" ::"r"(d), "l"(src));
}

__device__ __forceinline__ void prefetch_tile(__half* buf, int rowbase, int tid) {
    const float4* src = (const float4*)g_Y;   // 8 halves per float4, 8 per row
#pragma unroll
    for (int it = 0; it < 4; it++) {
        int u   = tid + it * 256;             // 0..1023
        int row = u >> 3;
        int kc  = u & 7;
        cp16(buf + row * 72 + kc * 8, src + (rowbase + row) * 8 + kc);
    }
}

__global__ void __launch_bounds__(256, 1) k_main() {
    extern __shared__ __align__(16) unsigned char sm[];
    __half* bufA = (__half*)sm;                         // [2][128*72]
    __half* bufB = (__half*)(sm + SM_B_BYTE);           // [2][128*72]
    float (*red)[4]  = (float(*)[4])(sm + SM_RED_BYTE);   // rowsum x 4 colgrp
    float (*cred)[2] = (float(*)[2])(sm + SM_CRED_BYTE);  // colsum x 2 rowgrp

    int tid  = threadIdx.x;
    int warp = tid >> 5, lane = tid & 31;
    int r = warp >> 2, c = warp & 3;
    int rbase = r * 64;
    int lr  = lane >> 2;                      // 0..7
    int lk2 = (lane & 3) * 2;                 // 0,2,4,6

    int start = (int)(((long long)TOT * blockIdx.x) / gridDim.x);
    int end   = (int)(((long long)TOT * (blockIdx.x + 1)) / gridDim.x);

    // locate starting (I, J) in row-major upper triangle
    int I = 0, acc = 0;
    while (acc + (NT - I) <= start) { acc += NT - I; I++; }
    int J = I + (start - acc);

    prefetch_tile(bufA, I * 128, tid);
    prefetch_tile(bufB, J * 128, tid);
    asm volatile("cp.async.commit_group;\n");

    for (int p = start; p < end; p++) {
        int buf = (p - start) & 1;
        int nI = I, nJ = J + 1;
        if (nJ == NT) { nI++; nJ = nI; }
        if (p + 1 < end) {
            prefetch_tile(bufA + (buf ^ 1) * SM_TILE, nI * 128, tid);
            prefetch_tile(bufB + (buf ^ 1) * SM_TILE, nJ * 128, tid);
            asm volatile("cp.async.commit_group;\n");
            asm volatile("cp.async.wait_group 1;\n");
        } else {
            asm volatile("cp.async.wait_group 0;\n");
        }
        __syncthreads();

        const __half* smA = bufA + buf * SM_TILE;
        const __half* smB = bufB + buf * SM_TILE;

        // A fragments: a0:(row,k) a1:(row+8,k) a2:(row,k+8) a3:(row+8,k+8)
        unsigned a[4][4][4];
#pragma unroll
        for (int mf = 0; mf < 4; mf++) {
#pragma unroll
            for (int kf = 0; kf < 4; kf++) {
                const __half* ap = smA + (rbase + mf * 16 + lr) * 72 + kf * 16 + lk2;
                a[mf][kf][0] = *(const unsigned*)(ap);
                a[mf][kf][1] = *(const unsigned*)(ap + 8 * 72);
                a[mf][kf][2] = *(const unsigned*)(ap + 8);
                a[mf][kf][3] = *(const unsigned*)(ap + 8 * 72 + 8);
            }
        }

        unsigned racc0[4] = {0, 0, 0, 0};   // f16x2 row accumulators (row lr)
        unsigned racc1[4] = {0, 0, 0, 0};   // (row lr+8)
        unsigned cacc[4]  = {0, 0, 0, 0};   // f16x2 col accumulators per s

#pragma unroll
        for (int s = 0; s < 4; s++) {
            int n0 = (c + s * 4) * 8;
            unsigned b[4][2];
            const __half* bp = smB + (n0 + lr) * 72 + lk2;
#pragma unroll
            for (int kf = 0; kf < 4; kf++) {
                b[kf][0] = *(const unsigned*)(bp + kf * 16);
                b[kf][1] = *(const unsigned*)(bp + kf * 16 + 8);
            }
#pragma unroll
            for (int mf = 0; mf < 4; mf++) {
                unsigned d0 = 0, d1 = 0;
#pragma unroll
                for (int kf = 0; kf < 4; kf++) {
                    asm("mma.sync.aligned.m16n8k16.row.col.f16.f16.f16.f16 "
                        "{%0,%1},{%2,%3,%4,%5},{%6,%7},{%0,%1};\n"
                        : "+r"(d0), "+r"(d1)
                        : "r"(a[mf][kf][0]), "r"(a[mf][kf][1]),
                          "r"(a[mf][kf][2]), "r"(a[mf][kf][3]),
                          "r"(b[kf][0]), "r"(b[kf][1]));
                }
                unsigned e0, e1;
                asm("ex2.approx.f16x2 %0, %1;" : "=r"(e0) : "r"(d0));
                asm("ex2.approx.f16x2 %0, %1;" : "=r"(e1) : "r"(d1));
                asm("add.f16x2 %0, %0, %1;" : "+r"(racc0[mf]) : "r"(e0));
                asm("add.f16x2 %0, %0, %1;" : "+r"(racc1[mf]) : "r"(e1));
                asm("add.f16x2 %0, %0, %1;" : "+r"(cacc[s]) : "r"(e0));
                asm("add.f16x2 %0, %0, %1;" : "+r"(cacc[s]) : "r"(e1));
            }
        }

        // Row sums: lo+hi then reduce over lane&3 (the 4 col-group lanes).
#pragma unroll
        for (int mf = 0; mf < 4; mf++) {
            float2 f0 = __half22float2(*reinterpret_cast<__half2*>(&racc0[mf]));
            float2 f1 = __half22float2(*reinterpret_cast<__half2*>(&racc1[mf]));
            float v0 = f0.x + f0.y;
            float v1 = f1.x + f1.y;
            v0 += __shfl_xor_sync(0xffffffffu, v0, 1);
            v0 += __shfl_xor_sync(0xffffffffu, v0, 2);
            v1 += __shfl_xor_sync(0xffffffffu, v1, 1);
            v1 += __shfl_xor_sync(0xffffffffu, v1, 2);
            if ((lane & 3) == 0) {
                red[rbase + mf * 16 + lr][c]     = v0;
                red[rbase + mf * 16 + 8 + lr][c] = v1;
            }
        }
        // Col sums: reduce over lr (lanes stride 4) per (s, half).
#pragma unroll
        for (int s = 0; s < 4; s++) {
            float2 cf = __half22float2(*reinterpret_cast<__half2*>(&cacc[s]));
#pragma unroll
            for (int h = 0; h < 2; h++) {
                float v = h ? cf.y : cf.x;
                v += __shfl_xor_sync(0xffffffffu, v, 4);
                v += __shfl_xor_sync(0xffffffffu, v, 8);
                v += __shfl_xor_sync(0xffffffffu, v, 16);
                if (lr == 0)
                    cred[(c + s * 4) * 8 + (lane & 3) * 2 + h][r] = v;
            }
        }
        __syncthreads();

        if (tid < 128) {
            float rs = red[tid][0] + red[tid][1] + red[tid][2] + red[tid][3];
            atomicAdd(&g_RS[I * 128 + tid], rs);
            if (I != J) {
                float cs = cred[tid][0] + cred[tid][1];
                atomicAdd(&g_RS[J * 128 + tid], cs);
            }
        }
        __syncthreads();
        I = nI; J = nJ;
    }
}

// ---------------------------------------------------------------------------
// Kernel 3: numerator (positive pair), ratio, deterministic block partials.
// ---------------------------------------------------------------------------
__global__ void k_final() {
    __shared__ float redsm[8];
    int i = blockIdx.x * 256 + threadIdx.x;
    int j = i ^ 1;
    const __half2* yi = g_Y + i * 32;
    const __half2* yj = g_Y + j * 32;
    float dot = 0.f;
#pragma unroll
    for (int k = 0; k < 32; k++) {
        float2 av = __half22float2(yi[k]);
        float2 bv = __half22float2(yj[k]);
        dot += av.x * bv.x + av.y * bv.y;
    }
    float num   = exp2f(dot);                 // dot already carries 1/(T ln2)
    float ratio = num / (g_RS[i] - E2C);

    int lane = threadIdx.x & 31, w = threadIdx.x >> 5;
#pragma unroll
    for (int o = 16; o > 0; o >>= 1) ratio += __shfl_xor_sync(0xffffffffu, ratio, o);
    if (lane == 0) redsm[w] = ratio;
    __syncthreads();
    if (threadIdx.x < 8) {
        float v = redsm[threadIdx.x];
#pragma unroll
        for (int o = 4; o > 0; o >>= 1) v += __shfl_xor_sync(0x000000ffu, v, o);
        if (threadIdx.x == 0) g_part[blockIdx.x] = v;
    }
}

// ---------------------------------------------------------------------------
// Kernel 4: final deterministic reduce of 64 partials -> loss.
// ---------------------------------------------------------------------------
__global__ void k_loss(float* __restrict__ out) {
    __shared__ float w2[2];
    int t = threadIdx.x;            // 64 threads
    float v = g_part[t];
#pragma unroll
    for (int o = 16; o > 0; o >>= 1) v += __shfl_xor_sync(0xffffffffu, v, o);
    if ((t & 31) == 0) w2[t >> 5] = v;
    __syncthreads();
    if (t == 0) out[0] = -logf((w2[0] + w2[1]) * (1.0f / (float)NR));
}

// ---------------------------------------------------------------------------
extern "C" void kernel_launch(void* const* d_in, const int* in_sizes, int n_in,
                              void* d_out, int out_size) {
    const float* x = (const float*)d_in[0];
    cudaFuncSetAttribute(k_main, cudaFuncAttributeMaxDynamicSharedMemorySize,
                         SM_TOTAL_BYTE);
    k_normalize<<<NR / 8, 256>>>(x);     // 8 rows (warps) per block
    k_main<<<148, 256, SM_TOTAL_BYTE>>>();
    k_final<<<NR / 256, 256>>>();
    k_loss<<<1, 64>>>((float*)d_out);
}